// round 1
// baseline (speedup 1.0000x reference)
#include <cuda_runtime.h>
#include <cstdint>

#define NTEST  16384
#define NTRAIN 16384
#define DIM    192
#define KNN    5

#define BM 64
#define BN 64
#define NK4 (DIM/4)          // 48 float4 per row
#define SSTRIDE 196          // padded smem row stride in floats (S16 = 49, odd -> conflict-free LDS.128)
#define SMEM_FLOATS (2 * BM * SSTRIDE)
#define SMEM_BYTES  (SMEM_FLOATS * 4)

__device__ float g_ynorm[NTRAIN];   // 0.5 * ||y_j||^2

// ---------------------------------------------------------------------------
// Kernel 1: half squared norms of train rows. One warp per row.
// ---------------------------------------------------------------------------
__global__ void ynorm_kernel(const float* __restrict__ Htr) {
    int warp = (blockIdx.x * blockDim.x + threadIdx.x) >> 5;
    int lane = threadIdx.x & 31;
    if (warp >= NTRAIN) return;
    const float* row = Htr + (size_t)warp * DIM;
    float s = 0.f;
#pragma unroll
    for (int i = 0; i < DIM / 32; i++) {
        float v = row[lane + 32 * i];
        s = fmaf(v, v, s);
    }
#pragma unroll
    for (int off = 16; off; off >>= 1)
        s += __shfl_xor_sync(0xffffffffu, s, off);
    if (lane == 0) g_ynorm[warp] = 0.5f * s;
}

// ---------------------------------------------------------------------------
// Kernel 2: fused score GEMM + per-row top-5 + p_hat gather.
// Block: 256 threads handles BM=64 test rows; streams train set in BN=64 tiles.
// Thread (ty,tx) in 16x16 grid owns rows {ty+16*i} x cols {tx+16*i} (4x4).
// ---------------------------------------------------------------------------
extern __shared__ float smem[];

__global__ void __launch_bounds__(256, 2)
knn_kernel(const float* __restrict__ Hte, const float* __restrict__ Htr,
           const float* __restrict__ phat, float* __restrict__ out)
{
    float* As = smem;                 // [BM][SSTRIDE]
    float* Bs = smem + BM * SSTRIDE;  // [BN][SSTRIDE]

    const int t  = threadIdx.x;
    const int tx = t & 15;
    const int ty = t >> 4;
    const int m0 = blockIdx.x * BM;

    // Load the A tile (test rows) once. Coalesced float4 along D.
    for (int idx = t; idx < BM * NK4; idx += 256) {
        int n = idx / NK4, k4 = idx % NK4;
        float4 v = *(const float4*)(Hte + (size_t)(m0 + n) * DIM + 4 * k4);
        *(float4*)(As + n * SSTRIDE + 4 * k4) = v;
    }

    // Register-resident top-5 per owned row (descending sorted).
    float ts[4][5];
    int   ti[4][5];
#pragma unroll
    for (int r = 0; r < 4; r++)
#pragma unroll
        for (int q = 0; q < 5; q++) { ts[r][q] = -1e30f; ti[r][q] = 0; }

    for (int j0 = 0; j0 < NTRAIN; j0 += BN) {
        __syncthreads();   // previous tile's consumers done (and A-tile ready on iter 0)
        for (int idx = t; idx < BN * NK4; idx += 256) {
            int n = idx / NK4, k4 = idx % NK4;
            float4 v = *(const float4*)(Htr + (size_t)(j0 + n) * DIM + 4 * k4);
            *(float4*)(Bs + n * SSTRIDE + 4 * k4) = v;
        }
        __syncthreads();

        float acc[4][4];
#pragma unroll
        for (int mi = 0; mi < 4; mi++)
#pragma unroll
            for (int ni = 0; ni < 4; ni++) acc[mi][ni] = 0.f;

        const float* ap = As + ty * SSTRIDE;
        const float* bp = Bs + tx * SSTRIDE;
#pragma unroll 4
        for (int k4 = 0; k4 < NK4; k4++) {
            float4 a[4], b[4];
#pragma unroll
            for (int i = 0; i < 4; i++)
                a[i] = *(const float4*)(ap + i * 16 * SSTRIDE + 4 * k4);
#pragma unroll
            for (int i = 0; i < 4; i++)
                b[i] = *(const float4*)(bp + i * 16 * SSTRIDE + 4 * k4);
#pragma unroll
            for (int mi = 0; mi < 4; mi++)
#pragma unroll
                for (int ni = 0; ni < 4; ni++) {
                    acc[mi][ni] = fmaf(a[mi].x, b[ni].x, acc[mi][ni]);
                    acc[mi][ni] = fmaf(a[mi].y, b[ni].y, acc[mi][ni]);
                    acc[mi][ni] = fmaf(a[mi].z, b[ni].z, acc[mi][ni]);
                    acc[mi][ni] = fmaf(a[mi].w, b[ni].w, acc[mi][ni]);
                }
        }

        // Top-5 update: score = dot - 0.5*||y||^2 (x-norm is row-constant).
#pragma unroll
        for (int ni = 0; ni < 4; ni++) {
            const int j = j0 + tx + 16 * ni;
            const float yn = __ldg(&g_ynorm[j]);
#pragma unroll
            for (int mi = 0; mi < 4; mi++) {
                const float v = acc[mi][ni] - yn;
                if (v > ts[mi][4]) {
                    ts[mi][4] = v; ti[mi][4] = j;
#pragma unroll
                    for (int q = 4; q > 0; q--) {
                        if (ts[mi][q] > ts[mi][q - 1]) {
                            float tv = ts[mi][q]; ts[mi][q] = ts[mi][q - 1]; ts[mi][q - 1] = tv;
                            int   tj = ti[mi][q]; ti[mi][q] = ti[mi][q - 1]; ti[mi][q - 1] = tj;
                        }
                    }
                }
            }
        }
    }

    // ---- Epilogue: merge 16 partial top-5 lists per row, gather p_hat ----
    __syncthreads();
    float* cs = smem;                        // [BM][80] scores
    int*   ci = (int*)(smem + BM * 80);      // [BM][80] indices
#pragma unroll
    for (int r = 0; r < 4; r++) {
        const int row = ty + 16 * r;
#pragma unroll
        for (int q = 0; q < 5; q++) {
            cs[row * 80 + tx * 5 + q] = ts[r][q];
            ci[row * 80 + tx * 5 + q] = ti[r][q];
        }
    }
    __syncthreads();

    if (t < BM) {
        float bs[5]; int bi[5];
#pragma unroll
        for (int q = 0; q < 5; q++) { bs[q] = -1e30f; bi[q] = 0; }
        for (int c = 0; c < 80; c++) {
            const float v = cs[t * 80 + c];
            if (v > bs[4]) {
                const int id = ci[t * 80 + c];
                bs[4] = v; bi[4] = id;
#pragma unroll
                for (int q = 4; q > 0; q--) {
                    if (bs[q] > bs[q - 1]) {
                        float tv = bs[q]; bs[q] = bs[q - 1]; bs[q - 1] = tv;
                        int   tj = bi[q]; bi[q] = bi[q - 1]; bi[q - 1] = tj;
                    }
                }
            }
        }
        float s0 = 0.f, s1 = 0.f;
#pragma unroll
        for (int q = 0; q < KNN; q++) {
            s0 += __ldg(phat + bi[q]);
            s1 += __ldg(phat + NTRAIN + bi[q]);
        }
        out[m0 + t]         = s0 * 0.2f;
        out[NTEST + m0 + t] = s1 * 0.2f;
    }
}

// ---------------------------------------------------------------------------
extern "C" void kernel_launch(void* const* d_in, const int* in_sizes, int n_in,
                              void* d_out, int out_size) {
    const float* Hte = (const float*)d_in[0];   // [16384, 192]
    const float* Htr = (const float*)d_in[1];   // [16384, 192]
    const float* ph  = (const float*)d_in[2];   // [2, 16384]
    float* out = (float*)d_out;                 // [2, 16384]

    cudaFuncSetAttribute(knn_kernel, cudaFuncAttributeMaxDynamicSharedMemorySize, SMEM_BYTES);

    ynorm_kernel<<<NTRAIN / 8, 256>>>(Htr);
    knn_kernel<<<NTEST / BM, 256, SMEM_BYTES>>>(Hte, Htr, ph, out);
}

// round 4
// speedup vs baseline: 1.0145x; 1.0145x over previous
#include <cuda_runtime.h>
#include <cstdint>

#define NTEST  16384
#define NTRAIN 16384
#define DIM    192
#define KNN    5

#define BM 128
#define BN 128
#define NK4 (DIM/4)           // 48 float4 per row
#define NKP (DIM/2)           // 96 float-pairs per row
#define SSTRIDE 196           // smem tile row stride (floats); 196*4B, 16B-aligned rows
#define SCST 129              // score matrix row stride (floats) -> conflict-free scan
#define SMEM_BYTES (2 * BM * SSTRIDE * 4)   // 200704 B

typedef unsigned long long ull;

__device__ float g_ynorm[NTRAIN];   // 0.5 * ||y_j||^2

// packed f32x2 FMA: acc(lo,hi) += a(lo,hi) * b(lo,hi), each lane exact fp32
#define FMA2(acc, a, b) \
    asm("fma.rn.f32x2 %0, %1, %2, %0;" : "+l"(acc) : "l"(a), "l"(b))

__device__ __forceinline__ float ull_lo(ull v) { return __uint_as_float((unsigned)v); }
__device__ __forceinline__ float ull_hi(ull v) { return __uint_as_float((unsigned)(v >> 32)); }

// order-preserving map: float -> uint such that larger float => larger uint
__device__ __forceinline__ unsigned fmap(float f) {
    unsigned u = __float_as_uint(f);
    return (u & 0x80000000u) ? ~u : (u | 0x80000000u);
}

// key encoding of -inf score (so initial entries lose to any finite score)
#define INIT_KEY (((ull)0x007FFFFFu) << 32)

// ---------------------------------------------------------------------------
// Kernel 1: half squared norms of train rows. One warp per row.
// ---------------------------------------------------------------------------
__global__ void ynorm_kernel(const float* __restrict__ Htr) {
    int warp = (blockIdx.x * blockDim.x + threadIdx.x) >> 5;
    int lane = threadIdx.x & 31;
    if (warp >= NTRAIN) return;
    const float* row = Htr + (size_t)warp * DIM;
    float s = 0.f;
#pragma unroll
    for (int i = 0; i < DIM / 32; i++) {
        float v = row[lane + 32 * i];
        s = fmaf(v, v, s);
    }
#pragma unroll
    for (int off = 16; off; off >>= 1)
        s += __shfl_xor_sync(0xffffffffu, s, off);
    if (lane == 0) g_ynorm[warp] = 0.5f * s;
}

// ---------------------------------------------------------------------------
// Kernel 2: fused score GEMM (8x8 microtile, f32x2 FMA) + per-row top-5 +
// p_hat gather. Block: 256 threads, tile 128x128, streams train in BN tiles.
// After each tile GEMM, scores are staged in (dead) B-tile smem; threads
// 0..127 each scan one full test row and keep top-5 as packed (key|idx).
// ---------------------------------------------------------------------------
extern __shared__ float smem[];

__global__ void __launch_bounds__(256, 1)
knn_kernel(const float* __restrict__ Hte, const float* __restrict__ Htr,
           const float* __restrict__ phat, float* __restrict__ out)
{
    float* As = smem;                 // [BM][SSTRIDE]
    float* Bs = smem + BM * SSTRIDE;  // [BN][SSTRIDE]
    float* Sc = Bs;                   // score staging aliases B tile: [BM][SCST]

    const int t  = threadIdx.x;
    const int tx = t & 15;
    const int ty = t >> 4;
    const int m0 = blockIdx.x * BM;

    // Load A tile (test rows) once; coalesced float4 along D.
    for (int idx = t; idx < BM * NK4; idx += 256) {
        int n = idx / NK4, k4 = idx % NK4;
        float4 v = *(const float4*)(Hte + (size_t)(m0 + n) * DIM + 4 * k4);
        *(float4*)(As + n * SSTRIDE + 4 * k4) = v;
    }

    // Per-row top-5 (threads 0..127 own row m0+t), packed (mapped_score<<32|col).
    ull best0 = INIT_KEY, best1 = INIT_KEY, best2 = INIT_KEY,
        best3 = INIT_KEY, best4 = INIT_KEY;

    for (int j0 = 0; j0 < NTRAIN; j0 += BN) {
        __syncthreads();   // prev scan done (and A load done on iter 0)

        // Load B tile (train rows).
        for (int idx = t; idx < BN * NK4; idx += 256) {
            int n = idx / NK4, k4 = idx % NK4;
            float4 v = *(const float4*)(Htr + (size_t)(j0 + n) * DIM + 4 * k4);
            *(float4*)(Bs + n * SSTRIDE + 4 * k4) = v;
        }
        __syncthreads();

        // 8x8 f32x2 GEMM: rows ty+16j, cols tx+16i.
        ull acc[8][8];
#pragma unroll
        for (int j = 0; j < 8; j++)
#pragma unroll
            for (int i = 0; i < 8; i++) acc[j][i] = 0ull;

        const float* ap = As + ty * SSTRIDE;
        const float* bp = Bs + tx * SSTRIDE;
#pragma unroll 4
        for (int kp = 0; kp < NKP; kp++) {
            ull a2[8], b2[8];
#pragma unroll
            for (int j = 0; j < 8; j++)
                a2[j] = *(const ull*)(ap + j * 16 * SSTRIDE + 2 * kp);
#pragma unroll
            for (int i = 0; i < 8; i++)
                b2[i] = *(const ull*)(bp + i * 16 * SSTRIDE + 2 * kp);
#pragma unroll
            for (int j = 0; j < 8; j++)
#pragma unroll
                for (int i = 0; i < 8; i++)
                    FMA2(acc[j][i], a2[j], b2[i]);
        }

        __syncthreads();   // GEMM reads of Bs done before overwriting with scores

        // Stage scores (dot - 0.5||y||^2) into smem.
#pragma unroll
        for (int i = 0; i < 8; i++) {
            const int col = tx + 16 * i;
            const float yn = __ldg(&g_ynorm[j0 + col]);
#pragma unroll
            for (int j = 0; j < 8; j++) {
                const ull v = acc[j][i];
                Sc[(ty + 16 * j) * SCST + col] = (ull_lo(v) + ull_hi(v)) - yn;
            }
        }
        __syncthreads();

        // Threads 0..127: scan one full row, maintain packed top-5.
        if (t < BM) {
            const float* srow = Sc + t * SCST;
#pragma unroll 4
            for (int c = 0; c < BN; c++) {
                const float s = srow[c];
                const ull key = (((ull)fmap(s)) << 32) | (unsigned)(j0 + c);
                if (key > best4) {
                    best4 = key;
                    ull tmp;
                    if (best4 > best3) { tmp = best4; best4 = best3; best3 = tmp; }
                    if (best3 > best2) { tmp = best3; best3 = best2; best2 = tmp; }
                    if (best2 > best1) { tmp = best2; best2 = best1; best1 = tmp; }
                    if (best1 > best0) { tmp = best1; best1 = best0; best0 = tmp; }
                }
            }
        }
    }

    // Epilogue: gather p_hat over top-5 neighbor columns, mean, write out.
    if (t < BM) {
        const int i0 = (int)(unsigned)best0;
        const int i1 = (int)(unsigned)best1;
        const int i2 = (int)(unsigned)best2;
        const int i3 = (int)(unsigned)best3;
        const int i4 = (int)(unsigned)best4;
        float s0 = __ldg(phat + i0) + __ldg(phat + i1) + __ldg(phat + i2)
                 + __ldg(phat + i3) + __ldg(phat + i4);
        float s1 = __ldg(phat + NTRAIN + i0) + __ldg(phat + NTRAIN + i1)
                 + __ldg(phat + NTRAIN + i2) + __ldg(phat + NTRAIN + i3)
                 + __ldg(phat + NTRAIN + i4);
        out[m0 + t]         = s0 * 0.2f;
        out[NTEST + m0 + t] = s1 * 0.2f;
    }
}

// ---------------------------------------------------------------------------
extern "C" void kernel_launch(void* const* d_in, const int* in_sizes, int n_in,
                              void* d_out, int out_size) {
    const float* Hte = (const float*)d_in[0];   // [16384, 192]
    const float* Htr = (const float*)d_in[1];   // [16384, 192]
    const float* ph  = (const float*)d_in[2];   // [2, 16384]
    float* out = (float*)d_out;                 // [2, 16384]

    cudaFuncSetAttribute(knn_kernel, cudaFuncAttributeMaxDynamicSharedMemorySize, SMEM_BYTES);

    ynorm_kernel<<<NTRAIN / 8, 256>>>(Htr);
    knn_kernel<<<NTEST / BM, 256, SMEM_BYTES>>>(Hte, Htr, ph, out);
}

// round 9
// speedup vs baseline: 2.0039x; 1.9753x over previous
#include <cuda_runtime.h>
#include <cuda_bf16.h>
#include <cstdint>

#define NTEST  16384
#define NTRAIN 16384
#define DIM    192
#define BM 128
#define BN 64
#define NTILES 256
#define KSPLIT 384
#define ROWB   768                 // bytes per split row
#define NG     (NTILES * 2)        // 512 k-chunks total (2 per tile)

#define ASTRB  784                 // A smem row stride bytes (392 bf16; 49*16B, odd -> conflict-free ldmatrix)
#define BSTRB  400                 // B smem row stride bytes (200 bf16; 25*16B, odd)
#define SCSTR  65                  // score row stride (floats)

#define SM_A   0                   // 128 * 784 = 100352
#define SM_B0  100352              // 64 * 400 = 25600
#define SM_B1  125952
#define SM_SC  151552              // 128 * 65 * 4 = 33280
#define SM_YNS 184832              // 64 floats
#define SMEM_BYTES (185088 + 256)

typedef unsigned long long ull;

__device__ float g_ynorm[NTRAIN];
__device__ __nv_bfloat16 g_Ate[(size_t)NTEST * KSPLIT];
__device__ __nv_bfloat16 g_Btr[(size_t)NTRAIN * KSPLIT];
__device__ int g_cand[NTEST * 8];

__device__ __forceinline__ uint32_t smem_u32(const void* p) {
    uint32_t a;
    asm("{ .reg .u64 t; cvta.to.shared.u64 t, %1; cvt.u32.u64 %0, t; }" : "=r"(a) : "l"(p));
    return a;
}
#define CP16(dst, src) asm volatile("cp.async.cg.shared.global [%0], [%1], 16;" :: "r"(dst), "l"(src))
#define CP_COMMIT() asm volatile("cp.async.commit_group;" ::: "memory")
#define CP_WAIT(n)  asm volatile("cp.async.wait_group %0;" :: "n"(n) : "memory")

#define LDSM4(r, a) asm volatile( \
    "ldmatrix.sync.aligned.m8n8.x4.shared.b16 {%0,%1,%2,%3}, [%4];" \
    : "=r"((r)[0]), "=r"((r)[1]), "=r"((r)[2]), "=r"((r)[3]) : "r"(a))

#define MMA16816(d, a, b0, b1) asm volatile( \
    "mma.sync.aligned.m16n8k16.row.col.f32.bf16.bf16.f32 " \
    "{%0,%1,%2,%3},{%4,%5,%6,%7},{%8,%9},{%0,%1,%2,%3};" \
    : "+f"((d)[0]), "+f"((d)[1]), "+f"((d)[2]), "+f"((d)[3]) \
    : "r"((a)[0]), "r"((a)[1]), "r"((a)[2]), "r"((a)[3]), "r"(b0), "r"(b1))

__device__ __forceinline__ unsigned fmap(float f) {
    unsigned u = __float_as_uint(f);
    return (u & 0x80000000u) ? ~u : (u | 0x80000000u);
}
#define INS8(key) do { ull _k=(key); if (_k > b7) { b7=_k; ull _t;            \
    if(b7>b6){_t=b7;b7=b6;b6=_t;} if(b6>b5){_t=b6;b6=b5;b5=_t;}              \
    if(b5>b4){_t=b5;b5=b4;b4=_t;} if(b4>b3){_t=b4;b4=b3;b3=_t;}              \
    if(b3>b2){_t=b3;b3=b2;b2=_t;} if(b2>b1){_t=b2;b2=b1;b1=_t;}              \
    if(b1>b0){_t=b1;b1=b0;b0=_t;} } } while (0)
#define INS5(key) do { ull _k=(key); if (_k > s4) { s4=_k; ull _t;            \
    if(s4>s3){_t=s4;s4=s3;s3=_t;} if(s3>s2){_t=s3;s3=s2;s2=_t;}              \
    if(s2>s1){_t=s2;s2=s1;s1=_t;} if(s1>s0){_t=s1;s1=s0;s0=_t;} } } while (0)

// ---------- prep kernels ----------
__global__ void ynorm_kernel(const float* __restrict__ Htr) {
    int w = (blockIdx.x * blockDim.x + threadIdx.x) >> 5, l = threadIdx.x & 31;
    if (w >= NTRAIN) return;
    const float* row = Htr + (size_t)w * DIM;
    float s = 0.f;
#pragma unroll
    for (int i = 0; i < 6; i++) { float v = row[l + 32 * i]; s = fmaf(v, v, s); }
#pragma unroll
    for (int o = 16; o; o >>= 1) s += __shfl_xor_sync(~0u, s, o);
    if (l == 0) g_ynorm[w] = 0.5f * s;
}
// dst = 0 -> g_Ate (test), 1 -> g_Btr (train). Row layout: [hi(192) | lo(192)].
__global__ void split_kernel(const float* __restrict__ X, int dst) {
    int i = blockIdx.x * blockDim.x + threadIdx.x;
    if (i >= NTEST * DIM) return;
    __nv_bfloat16* Y = dst ? g_Btr : g_Ate;
    int r = i / DIM, k = i % DIM;
    float a = X[i];
    __nv_bfloat16 h = __float2bfloat16(a);
    Y[(size_t)r * KSPLIT + k] = h;
    Y[(size_t)r * KSPLIT + DIM + k] = __float2bfloat16(a - __bfloat162float(h));
}

// ---------- main HMMA kernel ----------
extern __shared__ float4 smemv[];
__global__ void __launch_bounds__(256, 1)
knn_kernel()
{
    char* sm = (char*)smemv;
    const uint32_t sbase = smem_u32(sm);
    const int t = threadIdx.x, wid = t >> 5, lane = t & 31;
    const int wm = wid & 3, wn = wid >> 2;       // warp grid 4 (m) x 2 (n)
    const int lrow = lane & 15, lhalf = lane >> 4;
    const int m0 = blockIdx.x * BM;

    // A tile (group 0, together with B tile0 chunk0)
    {
        const char* gA = (const char*)(g_Ate + (size_t)m0 * KSPLIT);
        for (int i = t; i < BM * 48; i += 256) {
            int r = i / 48, q = i % 48;
            CP16(sbase + SM_A + r * ASTRB + q * 16, gA + (size_t)r * ROWB + q * 16);
        }
        const char* gB = (const char*)g_Btr;
        for (int i = t; i < BN * 24; i += 256) {
            int r = i / 24, q = i % 24;
            CP16(sbase + SM_B0 + r * BSTRB + q * 16, gB + (size_t)r * ROWB + q * 16);
        }
        CP_COMMIT();
    }

    float* SC  = (float*)(sm + SM_SC);
    float* yns = (float*)(sm + SM_YNS);
    ull b0=0,b1=0,b2=0,b3=0,b4=0,b5=0,b6=0,b7=0;
    float acc[2][4][4];

    for (int g = 0; g < NG; g++) {
        const int tile = g >> 1, c = g & 1, buf = g & 1;

        if (g + 1 < NG) {   // prefetch next k-chunk into the other buffer
            const int nt = (g + 1) >> 1, nc = (g + 1) & 1;
            const uint32_t bdst = sbase + (((g + 1) & 1) ? SM_B1 : SM_B0);
            const char* gB = (const char*)g_Btr + (size_t)(nt * BN) * ROWB + nc * 384;
            for (int i = t; i < BN * 24; i += 256) {
                int r = i / 24, q = i % 24;
                CP16(bdst + r * BSTRB + q * 16, gB + (size_t)r * ROWB + q * 16);
            }
            CP_COMMIT();
            CP_WAIT(1);
        } else CP_WAIT(0);
        __syncthreads();

        if (c == 0) {
            if (t < BN) yns[t] = g_ynorm[tile * BN + t];
#pragma unroll
            for (int mf = 0; mf < 2; mf++)
#pragma unroll
                for (int nf = 0; nf < 4; nf++)
#pragma unroll
                    for (int e = 0; e < 4; e++) acc[mf][nf][e] = 0.f;
        }

        // 12 k16 steps over this 192-wide chunk
        const uint32_t abase = sbase + SM_A + (uint32_t)((wm * 32 + lrow) * ASTRB) + c * 384 + lhalf * 16;
        const uint32_t bbase = sbase + (buf ? SM_B1 : SM_B0) + (uint32_t)((wn * 32 + lrow) * BSTRB) + lhalf * 16;
#pragma unroll
        for (int ks = 0; ks < 12; ks++) {
            uint32_t rA0[4], rA1[4], rB0[4], rB1[4];
            LDSM4(rA0, abase + ks * 32);
            LDSM4(rA1, abase + 16 * ASTRB + ks * 32);
            LDSM4(rB0, bbase + ks * 32);
            LDSM4(rB1, bbase + 16 * BSTRB + ks * 32);
            MMA16816(acc[0][0], rA0, rB0[0], rB0[2]);
            MMA16816(acc[0][1], rA0, rB0[1], rB0[3]);
            MMA16816(acc[0][2], rA0, rB1[0], rB1[2]);
            MMA16816(acc[0][3], rA0, rB1[1], rB1[3]);
            MMA16816(acc[1][0], rA1, rB0[0], rB0[2]);
            MMA16816(acc[1][1], rA1, rB0[1], rB0[3]);
            MMA16816(acc[1][2], rA1, rB1[0], rB1[2]);
            MMA16816(acc[1][3], rA1, rB1[1], rB1[3]);
        }
        __syncthreads();   // compute done before next prefetch overwrites this buffer

        if (c == 1) {
            // stage scores (dot - 0.5||y||^2) into SC
            const int mr = lane >> 2, nc2 = 2 * (lane & 3);
#pragma unroll
            for (int mf = 0; mf < 2; mf++)
#pragma unroll
                for (int nf = 0; nf < 4; nf++) {
                    int m = wm * 32 + mf * 16 + mr;
                    int n = wn * 32 + nf * 8 + nc2;
                    float y0 = yns[n], y1 = yns[n + 1];
                    SC[m * SCSTR + n]           = acc[mf][nf][0] - y0;
                    SC[m * SCSTR + n + 1]       = acc[mf][nf][1] - y1;
                    SC[(m + 8) * SCSTR + n]     = acc[mf][nf][2] - y0;
                    SC[(m + 8) * SCSTR + n + 1] = acc[mf][nf][3] - y1;
                }
            __syncthreads();
            if (t < BM) {   // per-row top-8 scan
                const float* srow = SC + t * SCSTR;
                const int jb = tile * BN;
#pragma unroll 4
                for (int cc = 0; cc < BN; cc++)
                    INS8(((ull)fmap(srow[cc]) << 32) | (unsigned)(jb + cc));
            }
        }
    }

    if (t < BM) {
        int* cp = g_cand + (m0 + t) * 8;
        cp[0]=(int)(unsigned)b0; cp[1]=(int)(unsigned)b1; cp[2]=(int)(unsigned)b2; cp[3]=(int)(unsigned)b3;
        cp[4]=(int)(unsigned)b4; cp[5]=(int)(unsigned)b5; cp[6]=(int)(unsigned)b6; cp[7]=(int)(unsigned)b7;
    }
}

// ---------- exact rescore: one warp per test row ----------
__global__ void rescore_kernel(const float* __restrict__ Hte, const float* __restrict__ Htr,
                               const float* __restrict__ phat, float* __restrict__ out)
{
    const int w = (blockIdx.x * blockDim.x + threadIdx.x) >> 5;
    const int lane = threadIdx.x & 31;
    if (w >= NTEST) return;
    const int g = lane >> 2, part = lane & 3;
    const int cidx = g_cand[w * 8 + g];
    const float4* te = (const float4*)(Hte + (size_t)w * DIM) + part * 12;
    const float4* tr = (const float4*)(Htr + (size_t)cidx * DIM) + part * 12;
    float a = 0.f;
#pragma unroll
    for (int i = 0; i < 12; i++) {
        float4 x = te[i], y = tr[i];
        a = fmaf(x.x, y.x, fmaf(x.y, y.y, fmaf(x.z, y.z, fmaf(x.w, y.w, a))));
    }
    a += __shfl_xor_sync(~0u, a, 1);
    a += __shfl_xor_sync(~0u, a, 2);
    const ull key = ((ull)fmap(a - g_ynorm[cidx]) << 32) | (unsigned)cidx;

    ull s0=0, s1=0, s2=0, s3=0, s4=0;
#pragma unroll
    for (int q = 0; q < 8; q++) {
        ull k = __shfl_sync(~0u, key, q * 4);
        INS5(k);
    }
    if (lane == 0) {
        int i0=(int)(unsigned)s0, i1=(int)(unsigned)s1, i2=(int)(unsigned)s2,
            i3=(int)(unsigned)s3, i4=(int)(unsigned)s4;
        float p0 = __ldg(phat+i0)+__ldg(phat+i1)+__ldg(phat+i2)+__ldg(phat+i3)+__ldg(phat+i4);
        float p1 = __ldg(phat+NTRAIN+i0)+__ldg(phat+NTRAIN+i1)+__ldg(phat+NTRAIN+i2)
                 + __ldg(phat+NTRAIN+i3)+__ldg(phat+NTRAIN+i4);
        out[w] = p0 * 0.2f;
        out[NTEST + w] = p1 * 0.2f;
    }
}

// ---------------------------------------------------------------------------
extern "C" void kernel_launch(void* const* d_in, const int* in_sizes, int n_in,
                              void* d_out, int out_size) {
    const float* Hte = (const float*)d_in[0];
    const float* Htr = (const float*)d_in[1];
    const float* ph  = (const float*)d_in[2];
    float* out = (float*)d_out;

    cudaFuncSetAttribute(knn_kernel, cudaFuncAttributeMaxDynamicSharedMemorySize, SMEM_BYTES);

    ynorm_kernel<<<NTRAIN / 8, 256>>>(Htr);
    split_kernel<<<(NTEST * DIM + 255) / 256, 256>>>(Hte, 0);
    split_kernel<<<(NTRAIN * DIM + 255) / 256, 256>>>(Htr, 1);
    knn_kernel<<<NTEST / BM, 256, SMEM_BYTES>>>();
    rescore_kernel<<<NTEST / 8, 256>>>(Hte, Htr, ph, out);
}

// round 14
// speedup vs baseline: 2.2316x; 1.1136x over previous
#include <cuda_runtime.h>
#include <cuda_bf16.h>
#include <cstdint>

#define NTEST  16384
#define NTRAIN 16384
#define DIM    192
#define BM 128
#define BN 64
#define NTILES 256
#define KSPLIT 384
#define ROWB   768                 // bytes per split row
#define NG     (NTILES * 2)        // 512 k-chunks (2 per tile)

#define ASTRB  784                 // A smem row stride bytes (49*16, odd -> conflict-free ldmatrix)
#define BSTRB  400                 // B smem row stride bytes (25*16, odd)
#define SCSTR  65                  // score row stride (floats)

#define SM_A   0                   // 128 * 784 = 100352
#define SM_B0  100352              // 64 * 400 = 25600
#define SM_B1  125952
#define SM_SC  151552              // 128 * 65 * 4 = 33280 (also reused as 128x32 ull merge area)
#define SM_YNS 184832              // 64 floats
#define SMEM_BYTES (185088 + 256)

#define NTHR 512

typedef unsigned long long ull;

__device__ float g_ynorm[NTRAIN];
__device__ __nv_bfloat16 g_Ate[(size_t)NTEST * KSPLIT];
__device__ __nv_bfloat16 g_Btr[(size_t)NTRAIN * KSPLIT];
__device__ int g_cand[NTEST * 8];

__device__ __forceinline__ uint32_t smem_u32(const void* p) {
    uint32_t a;
    asm("{ .reg .u64 t; cvta.to.shared.u64 t, %1; cvt.u32.u64 %0, t; }" : "=r"(a) : "l"(p));
    return a;
}
#define CP16(dst, src) asm volatile("cp.async.cg.shared.global [%0], [%1], 16;" :: "r"(dst), "l"(src))
#define CP_COMMIT() asm volatile("cp.async.commit_group;" ::: "memory")
#define CP_WAIT(n)  asm volatile("cp.async.wait_group %0;" :: "n"(n) : "memory")

#define LDSM4(r, a) asm volatile( \
    "ldmatrix.sync.aligned.m8n8.x4.shared.b16 {%0,%1,%2,%3}, [%4];" \
    : "=r"((r)[0]), "=r"((r)[1]), "=r"((r)[2]), "=r"((r)[3]) : "r"(a))

#define MMA16816(d, a, b0, b1) asm volatile( \
    "mma.sync.aligned.m16n8k16.row.col.f32.bf16.bf16.f32 " \
    "{%0,%1,%2,%3},{%4,%5,%6,%7},{%8,%9},{%0,%1,%2,%3};" \
    : "+f"((d)[0]), "+f"((d)[1]), "+f"((d)[2]), "+f"((d)[3]) \
    : "r"((a)[0]), "r"((a)[1]), "r"((a)[2]), "r"((a)[3]), "r"(b0), "r"(b1))

__device__ __forceinline__ unsigned fmap(float f) {
    unsigned u = __float_as_uint(f);
    return (u & 0x80000000u) ? ~u : (u | 0x80000000u);
}
#define INS8(key) do { ull _k=(key); if (_k > b7) { b7=_k; ull _t;            \
    if(b7>b6){_t=b7;b7=b6;b6=_t;} if(b6>b5){_t=b6;b6=b5;b5=_t;}              \
    if(b5>b4){_t=b5;b5=b4;b4=_t;} if(b4>b3){_t=b4;b4=b3;b3=_t;}              \
    if(b3>b2){_t=b3;b3=b2;b2=_t;} if(b2>b1){_t=b2;b2=b1;b1=_t;}              \
    if(b1>b0){_t=b1;b1=b0;b0=_t;} } } while (0)
#define INS5(key) do { ull _k=(key); if (_k > s4) { s4=_k; ull _t;            \
    if(s4>s3){_t=s4;s4=s3;s3=_t;} if(s3>s2){_t=s3;s3=s2;s2=_t;}              \
    if(s2>s1){_t=s2;s2=s1;s1=_t;} if(s1>s0){_t=s1;s1=s0;s0=_t;} } } while (0)

// ---------- prep kernels ----------
__global__ void ynorm_kernel(const float* __restrict__ Htr) {
    int w = (blockIdx.x * blockDim.x + threadIdx.x) >> 5, l = threadIdx.x & 31;
    if (w >= NTRAIN) return;
    const float* row = Htr + (size_t)w * DIM;
    float s = 0.f;
#pragma unroll
    for (int i = 0; i < 6; i++) { float v = row[l + 32 * i]; s = fmaf(v, v, s); }
#pragma unroll
    for (int o = 16; o; o >>= 1) s += __shfl_xor_sync(~0u, s, o);
    if (l == 0) g_ynorm[w] = 0.5f * s;
}
// dst = 0 -> g_Ate (test), 1 -> g_Btr (train). Row layout: [hi(192) | lo(192)].
__global__ void split_kernel(const float* __restrict__ X, int dst) {
    int i = blockIdx.x * blockDim.x + threadIdx.x;
    if (i >= NTEST * DIM) return;
    __nv_bfloat16* Y = dst ? g_Btr : g_Ate;
    int r = i / DIM, k = i % DIM;
    float a = X[i];
    __nv_bfloat16 h = __float2bfloat16(a);
    Y[(size_t)r * KSPLIT + k] = h;
    Y[(size_t)r * KSPLIT + DIM + k] = __float2bfloat16(a - __bfloat162float(h));
}

// ---------- main HMMA kernel: 512 threads, warp grid 4m x 4n ----------
extern __shared__ float4 smemv[];
__global__ void __launch_bounds__(NTHR, 1)
knn_kernel()
{
    char* sm = (char*)smemv;
    const uint32_t sbase = smem_u32(sm);
    const int t = threadIdx.x, wid = t >> 5, lane = t & 31;
    const int wm = wid & 3, wn = wid >> 2;       // 4 (m) x 4 (n)
    const int lrow = lane & 15, lhalf = lane >> 4;
    const int m0 = blockIdx.x * BM;

    // A tile + B tile0 chunk0
    {
        const char* gA = (const char*)(g_Ate + (size_t)m0 * KSPLIT);
        for (int i = t; i < BM * 48; i += NTHR) {
            int r = i / 48, q = i % 48;
            CP16(sbase + SM_A + r * ASTRB + q * 16, gA + (size_t)r * ROWB + q * 16);
        }
        const char* gB = (const char*)g_Btr;
        for (int i = t; i < BN * 24; i += NTHR) {
            int r = i / 24, q = i % 24;
            CP16(sbase + SM_B0 + r * BSTRB + q * 16, gB + (size_t)r * ROWB + q * 16);
        }
        CP_COMMIT();
    }

    float* SC  = (float*)(sm + SM_SC);
    float* yns = (float*)(sm + SM_YNS);
    const int srow_id = t & 127;    // scan: 4 threads per row
    const int ssid    = t >> 7;     // column slice 0..3
    ull b0=0,b1=0,b2=0,b3=0,b4=0,b5=0,b6=0,b7=0;
    float acc[2][2][4];

    for (int g = 0; g < NG; g++) {
        const int tile = g >> 1, c = g & 1, buf = g & 1;

        if (g + 1 < NG) {   // prefetch next k-chunk into the other buffer
            const int nt = (g + 1) >> 1, nc = (g + 1) & 1;
            const uint32_t bdst = sbase + (((g + 1) & 1) ? SM_B1 : SM_B0);
            const char* gB = (const char*)g_Btr + (size_t)(nt * BN) * ROWB + nc * 384;
            for (int i = t; i < BN * 24; i += NTHR) {
                int r = i / 24, q = i % 24;
                CP16(bdst + r * BSTRB + q * 16, gB + (size_t)r * ROWB + q * 16);
            }
            CP_COMMIT();
            CP_WAIT(1);
        } else CP_WAIT(0);
        __syncthreads();

        if (c == 0) {
            if (t < BN) yns[t] = g_ynorm[tile * BN + t];
#pragma unroll
            for (int mf = 0; mf < 2; mf++)
#pragma unroll
                for (int nf = 0; nf < 2; nf++)
#pragma unroll
                    for (int e = 0; e < 4; e++) acc[mf][nf][e] = 0.f;
        }

        // 12 k16 steps over this 192-wide chunk; warp tile 32m x 16n
        const uint32_t abase = sbase + SM_A + (uint32_t)((wm * 32 + lrow) * ASTRB) + c * 384 + lhalf * 16;
        const uint32_t bbase = sbase + (buf ? SM_B1 : SM_B0) + (uint32_t)((wn * 16 + lrow) * BSTRB) + lhalf * 16;
#pragma unroll
        for (int ks = 0; ks < 12; ks++) {
            uint32_t rA0[4], rA1[4], rB[4];
            LDSM4(rA0, abase + ks * 32);
            LDSM4(rA1, abase + 16 * ASTRB + ks * 32);
            LDSM4(rB,  bbase + ks * 32);
            MMA16816(acc[0][0], rA0, rB[0], rB[2]);
            MMA16816(acc[0][1], rA0, rB[1], rB[3]);
            MMA16816(acc[1][0], rA1, rB[0], rB[2]);
            MMA16816(acc[1][1], rA1, rB[1], rB[3]);
        }
        __syncthreads();   // compute done before next prefetch overwrites this buffer

        if (c == 1) {
            // stage scores (dot - 0.5||y||^2) into SC
            const int mr = lane >> 2, nc2 = 2 * (lane & 3);
#pragma unroll
            for (int mf = 0; mf < 2; mf++)
#pragma unroll
                for (int nf = 0; nf < 2; nf++) {
                    int m = wm * 32 + mf * 16 + mr;
                    int n = wn * 16 + nf * 8 + nc2;
                    float y0 = yns[n], y1 = yns[n + 1];
                    SC[m * SCSTR + n]           = acc[mf][nf][0] - y0;
                    SC[m * SCSTR + n + 1]       = acc[mf][nf][1] - y1;
                    SC[(m + 8) * SCSTR + n]     = acc[mf][nf][2] - y0;
                    SC[(m + 8) * SCSTR + n + 1] = acc[mf][nf][3] - y1;
                }
            __syncthreads();
            // per-row top-8 scan: 4 threads per row, 16 cols each
            {
                const float* srow = SC + srow_id * SCSTR + ssid * 16;
                const int jb = tile * BN + ssid * 16;
#pragma unroll 4
                for (int cc = 0; cc < 16; cc++)
                    INS8(((ull)fmap(srow[cc]) << 32) | (unsigned)(jb + cc));
            }
        }
    }

    // ---- final 32 -> 8 merge per row (reuse SC region as ull[128][32]) ----
    __syncthreads();
    ull* mg = (ull*)(sm + SM_SC);
    {
        ull* dst = mg + srow_id * 32 + ssid * 8;
        dst[0]=b0; dst[1]=b1; dst[2]=b2; dst[3]=b3;
        dst[4]=b4; dst[5]=b5; dst[6]=b6; dst[7]=b7;
    }
    __syncthreads();
    if (t < BM) {
        b0=b1=b2=b3=b4=b5=b6=b7=0;
        const ull* src = mg + t * 32;
#pragma unroll
        for (int i = 0; i < 32; i++) INS8(src[i]);
        int* cp = g_cand + (m0 + t) * 8;
        cp[0]=(int)(unsigned)b0; cp[1]=(int)(unsigned)b1; cp[2]=(int)(unsigned)b2; cp[3]=(int)(unsigned)b3;
        cp[4]=(int)(unsigned)b4; cp[5]=(int)(unsigned)b5; cp[6]=(int)(unsigned)b6; cp[7]=(int)(unsigned)b7;
    }
}

// ---------- exact rescore: one warp per test row ----------
__global__ void rescore_kernel(const float* __restrict__ Hte, const float* __restrict__ Htr,
                               const float* __restrict__ phat, float* __restrict__ out)
{
    const int w = (blockIdx.x * blockDim.x + threadIdx.x) >> 5;
    const int lane = threadIdx.x & 31;
    if (w >= NTEST) return;
    const int g = lane >> 2, part = lane & 3;
    const int cidx = g_cand[w * 8 + g];
    const float4* te = (const float4*)(Hte + (size_t)w * DIM) + part * 12;
    const float4* tr = (const float4*)(Htr + (size_t)cidx * DIM) + part * 12;
    float a = 0.f;
#pragma unroll
    for (int i = 0; i < 12; i++) {
        float4 x = te[i], y = tr[i];
        a = fmaf(x.x, y.x, fmaf(x.y, y.y, fmaf(x.z, y.z, fmaf(x.w, y.w, a))));
    }
    a += __shfl_xor_sync(~0u, a, 1);
    a += __shfl_xor_sync(~0u, a, 2);
    const ull key = ((ull)fmap(a - g_ynorm[cidx]) << 32) | (unsigned)cidx;

    ull s0=0, s1=0, s2=0, s3=0, s4=0;
#pragma unroll
    for (int q = 0; q < 8; q++) {
        ull k = __shfl_sync(~0u, key, q * 4);
        INS5(k);
    }
    if (lane == 0) {
        int i0=(int)(unsigned)s0, i1=(int)(unsigned)s1, i2=(int)(unsigned)s2,
            i3=(int)(unsigned)s3, i4=(int)(unsigned)s4;
        float p0 = __ldg(phat+i0)+__ldg(phat+i1)+__ldg(phat+i2)+__ldg(phat+i3)+__ldg(phat+i4);
        float p1 = __ldg(phat+NTRAIN+i0)+__ldg(phat+NTRAIN+i1)+__ldg(phat+NTRAIN+i2)
                 + __ldg(phat+NTRAIN+i3)+__ldg(phat+NTRAIN+i4);
        out[w] = p0 * 0.2f;
        out[NTEST + w] = p1 * 0.2f;
    }
}

// ---------------------------------------------------------------------------
extern "C" void kernel_launch(void* const* d_in, const int* in_sizes, int n_in,
                              void* d_out, int out_size) {
    const float* Hte = (const float*)d_in[0];
    const float* Htr = (const float*)d_in[1];
    const float* ph  = (const float*)d_in[2];
    float* out = (float*)d_out;

    cudaFuncSetAttribute(knn_kernel, cudaFuncAttributeMaxDynamicSharedMemorySize, SMEM_BYTES);

    ynorm_kernel<<<NTRAIN / 8, 256>>>(Htr);
    split_kernel<<<(NTEST * DIM + 255) / 256, 256>>>(Hte, 0);
    split_kernel<<<(NTRAIN * DIM + 255) / 256, 256>>>(Htr, 1);
    knn_kernel<<<NTEST / BM, NTHR, SMEM_BYTES>>>();
    rescore_kernel<<<NTEST / 8, 256>>>(Hte, Htr, ph, out);
}